// round 2
// baseline (speedup 1.0000x reference)
#include <cuda_runtime.h>

#define BB 8
#define SS 1024
#define EE 128
#define HH 8
#define DD 128

typedef unsigned long long ull;

// Scratch (static device globals -- no runtime allocation allowed)
__device__ float g_Q[(size_t)BB*HH*SS*DD];   // [B,H,S,D]
__device__ float g_K[(size_t)BB*HH*SS*DD];
__device__ float g_V[(size_t)BB*HH*SS*DD];
__device__ float g_O[(size_t)BB*SS*HH*DD];   // [B,S,H*D]

// ---- packed f32x2 helpers ----
__device__ __forceinline__ void ffma2(ull& d, ull a, ull b) {
    asm("fma.rn.f32x2 %0, %1, %2, %3;" : "=l"(d) : "l"(a), "l"(b), "l"(d));
}
__device__ __forceinline__ void fmul2(ull& d, ull a) {
    asm("mul.rn.f32x2 %0, %1, %2;" : "=l"(d) : "l"(d), "l"(a));
}
__device__ __forceinline__ ull fdup(float x) {
    unsigned u = __float_as_uint(x);
    return ((ull)u << 32) | (ull)u;
}
__device__ __forceinline__ float fsum2(ull p) {
    return __uint_as_float((unsigned)(p & 0xffffffffu)) +
           __uint_as_float((unsigned)(p >> 32));
}

// ---------------------------------------------------------------------------
// Fused QKV projection: out[m][n] = sum_k X[m][k]*W[n][k]
// M=8192, N=1024 (8 heads x 128), K=128.  CTA tile 128x128, 256 thr, 8x8/thr.
// Smem tiles XOR-swizzled: phys chunk4 = c4 ^ (row & 31), pitch 128.
// ---------------------------------------------------------------------------
__global__ __launch_bounds__(256) void qkv_proj_kernel(
    const float* __restrict__ q, const float* __restrict__ k, const float* __restrict__ v,
    const float* __restrict__ Wq, const float* __restrict__ Wk, const float* __restrict__ Wv)
{
    extern __shared__ float sm[];
    float* As = sm;              // [128][128] swizzled
    float* Bs = sm + 128*128;    // [128][128] swizzled

    const float* A; const float* W; float* O;
    if (blockIdx.z == 0)      { A = q; W = Wq; O = g_Q; }
    else if (blockIdx.z == 1) { A = k; W = Wk; O = g_K; }
    else                      { A = v; W = Wv; O = g_V; }

    const int m0 = blockIdx.y * 128;
    const int h  = blockIdx.x;
    const int tid = threadIdx.x;
    const int tx = tid & 15, ty = tid >> 4;

    #pragma unroll
    for (int t = 0; t < 16; t++) {
        int idx = tid + 256*t;
        int r = idx >> 5, c4 = idx & 31;
        int sw = ((c4 ^ (r & 31)) << 2);
        *(float4*)&As[r*128 + sw] = *(const float4*)(A + (size_t)(m0+r)*128 + c4*4);
        *(float4*)&Bs[r*128 + sw] = *(const float4*)(W + (size_t)(h*128+r)*128 + c4*4);
    }
    __syncthreads();

    ull acc[8][8];
    #pragma unroll
    for (int i = 0; i < 8; i++)
        #pragma unroll
        for (int j = 0; j < 8; j++) acc[i][j] = 0ULL;

    #pragma unroll 2
    for (int kk = 0; kk < 128; kk += 4) {
        int c4 = kk >> 2;
        ulonglong2 av[8], bv[8];
        #pragma unroll
        for (int i = 0; i < 8; i++) {
            int r = ty*8 + i;
            av[i] = *(const ulonglong2*)&As[r*128 + ((c4 ^ (r & 31)) << 2)];
        }
        #pragma unroll
        for (int j = 0; j < 8; j++) {
            int n = tx + 16*j;
            bv[j] = *(const ulonglong2*)&Bs[n*128 + ((c4 ^ (n & 31)) << 2)];
        }
        #pragma unroll
        for (int i = 0; i < 8; i++)
            #pragma unroll
            for (int j = 0; j < 8; j++) {
                ffma2(acc[i][j], av[i].x, bv[j].x);
                ffma2(acc[i][j], av[i].y, bv[j].y);
            }
    }

    #pragma unroll
    for (int i = 0; i < 8; i++) {
        int m = m0 + ty*8 + i;
        int b_ = m >> 10, s_ = m & 1023;
        float* op = O + (((size_t)(b_*HH + h))*SS + s_)*DD;
        #pragma unroll
        for (int j = 0; j < 8; j++)
            op[tx + 16*j] = fsum2(acc[i][j]);
    }
}

// ---------------------------------------------------------------------------
// Flash attention. CTA = 128 query rows of one (b,h). 256 threads.
// Thread: 8 rows (ty*8+i), QK cols tx+16*jj (jj<4), PV cols tx+16*jj (jj<8).
// Smem: Qs[128][128] sw4, Ks[64][128] sw4, Vst[128][64] (transposed, sw2),
//       Ps[128][68].
// Softmax fully in registers via shfl.xor over the 16 row-sharing lanes.
// ---------------------------------------------------------------------------
__global__ __launch_bounds__(256, 1) void attn_kernel(const float* __restrict__ mask)
{
    extern __shared__ float sm[];
    float* Qs  = sm;                  // 128*128
    float* Ks  = Qs  + 128*128;       // 64*128
    float* Vst = Ks  + 64*128;        // 128*64  (Vst[c][kq] swizzled in kq pairs)
    float* Ps  = Vst + 128*64;        // 128*68

    const int tid = threadIdx.x;
    const int tx = tid & 15, ty = tid >> 4;
    const int bh = blockIdx.y;
    const int b_ = bh >> 3, h = bh & 7;
    const int q0 = blockIdx.x * 128;
    const float* qp = g_Q + ((size_t)bh*SS + q0)*DD;
    const float* kp = g_K + (size_t)bh*SS*DD;
    const float* vp = g_V + (size_t)bh*SS*DD;
    const float* mb = mask + b_*SS;

    #pragma unroll
    for (int t = 0; t < 16; t++) {
        int idx = tid + 256*t;
        int r = idx >> 5, c4 = idx & 31;
        *(float4*)&Qs[r*128 + ((c4 ^ (r & 31)) << 2)] =
            *(const float4*)(qp + (size_t)r*128 + c4*4);
    }

    float m_prev[8], l_[8], alpha[8];
    #pragma unroll
    for (int i = 0; i < 8; i++) { m_prev[i] = -3.0e38f; l_[i] = 0.f; }

    ull o[8][8];
    #pragma unroll
    for (int i = 0; i < 8; i++)
        #pragma unroll
        for (int j = 0; j < 8; j++) o[i][j] = 0ULL;

    const float scale = 0.08838834764831845f;  // 1/sqrt(128)

    for (int j0 = 0; j0 < SS; j0 += 64) {
        __syncthreads();   // prior-iter PV reads done before overwrite
        // K tile
        #pragma unroll
        for (int t = 0; t < 8; t++) {
            int idx = tid + 256*t;
            int r = idx >> 5, c4 = idx & 31;
            *(float4*)&Ks[r*128 + ((c4 ^ (r & 31)) << 2)] =
                *(const float4*)(kp + (size_t)(j0+r)*128 + c4*4);
        }
        // V transposed: Vst[c][kq], kq-pair swizzle: off = c*64 + ((kq/2 ^ (c&31))*2 | kq&1)
        #pragma unroll
        for (int t = 0; t < 16; t++) {
            int idx = tid + 256*t;
            int kq = idx >> 6, c2 = idx & 63;
            float2 f = *(const float2*)(vp + (size_t)(j0+kq)*128 + c2*2);
            int c = c2*2;
            Vst[c*64     + ((((kq>>1) ^ (c     & 31)) << 1) | (kq & 1))] = f.x;
            Vst[(c+1)*64 + ((((kq>>1) ^ ((c+1) & 31)) << 1) | (kq & 1))] = f.y;
        }
        __syncthreads();

        float mv[4];
        #pragma unroll
        for (int jj = 0; jj < 4; jj++) mv[jj] = mb[j0 + tx + 16*jj];

        // QK^T + softmax in two 4-row halves (register pressure)
        #pragma unroll
        for (int half = 0; half < 2; half++) {
            ull acc[4][4];
            #pragma unroll
            for (int i = 0; i < 4; i++)
                #pragma unroll
                for (int j = 0; j < 4; j++) acc[i][j] = 0ULL;

            #pragma unroll 2
            for (int kk = 0; kk < 128; kk += 4) {
                int c4 = kk >> 2;
                ulonglong2 av[4], bv[4];
                #pragma unroll
                for (int i = 0; i < 4; i++) {
                    int r = ty*8 + half*4 + i;
                    av[i] = *(const ulonglong2*)&Qs[r*128 + ((c4 ^ (r & 31)) << 2)];
                }
                #pragma unroll
                for (int jj = 0; jj < 4; jj++) {
                    int n = tx + 16*jj;
                    bv[jj] = *(const ulonglong2*)&Ks[n*128 + ((c4 ^ (n & 31)) << 2)];
                }
                #pragma unroll
                for (int i = 0; i < 4; i++)
                    #pragma unroll
                    for (int jj = 0; jj < 4; jj++) {
                        ffma2(acc[i][jj], av[i].x, bv[jj].x);
                        ffma2(acc[i][jj], av[i].y, bv[jj].y);
                    }
            }

            #pragma unroll
            for (int i = 0; i < 4; i++) {
                int ri = half*4 + i;
                float s[4];
                float mx = -3.0e38f;
                #pragma unroll
                for (int jj = 0; jj < 4; jj++) {
                    s[jj] = fsum2(acc[i][jj]) * scale + mv[jj];
                    mx = fmaxf(mx, s[jj]);
                }
                #pragma unroll
                for (int msk = 1; msk <= 8; msk <<= 1)
                    mx = fmaxf(mx, __shfl_xor_sync(0xffffffffu, mx, msk));
                float mnew = fmaxf(m_prev[ri], mx);
                float al = __expf(m_prev[ri] - mnew);
                m_prev[ri] = mnew;
                float p[4], sum = 0.f;
                #pragma unroll
                for (int jj = 0; jj < 4; jj++) {
                    p[jj] = __expf(s[jj] - mnew);
                    sum += p[jj];
                }
                #pragma unroll
                for (int msk = 1; msk <= 8; msk <<= 1)
                    sum += __shfl_xor_sync(0xffffffffu, sum, msk);
                l_[ri] = l_[ri]*al + sum;
                alpha[ri] = al;
                int r = ty*8 + ri;
                #pragma unroll
                for (int jj = 0; jj < 4; jj++)
                    Ps[r*68 + tx + 16*jj] = p[jj];
            }
        }
        __syncthreads();

        // rescale O by alpha
        #pragma unroll
        for (int i = 0; i < 8; i++) {
            ull ad = fdup(alpha[i]);
            #pragma unroll
            for (int jj = 0; jj < 8; jj++) fmul2(o[i][jj], ad);
        }

        // O += P @ V   (packed over kq)
        #pragma unroll 2
        for (int kk = 0; kk < 64; kk += 4) {
            int k2 = kk >> 1;
            ulonglong2 pv[8];
            #pragma unroll
            for (int i = 0; i < 8; i++) {
                int r = ty*8 + i;
                pv[i] = *(const ulonglong2*)&Ps[r*68 + kk];
            }
            ull b0[8], b1[8];
            #pragma unroll
            for (int jj = 0; jj < 8; jj++) {
                int c = tx + 16*jj;
                const float* base = Vst + c*64;
                b0[jj] = *(const ull*)&base[((k2     ^ (c & 31)) << 1)];
                b1[jj] = *(const ull*)&base[(((k2+1) ^ (c & 31)) << 1)];
            }
            #pragma unroll
            for (int i = 0; i < 8; i++)
                #pragma unroll
                for (int jj = 0; jj < 8; jj++) {
                    ffma2(o[i][jj], pv[i].x, b0[jj]);
                    ffma2(o[i][jj], pv[i].y, b1[jj]);
                }
        }
    }

    // epilogue
    #pragma unroll
    for (int i = 0; i < 8; i++) {
        int r = ty*8 + i;
        float inv = 1.f / (l_[i] + 1e-12f);
        float* op = g_O + ((size_t)(b_*SS + q0 + r))*(HH*DD) + h*DD;
        #pragma unroll
        for (int jj = 0; jj < 8; jj++)
            op[tx + 16*jj] = fsum2(o[i][jj]) * inv;
    }
}

// ---------------------------------------------------------------------------
// Output projection: out[m][n] = sum_k O[m][k]*Wc[n][k] + bc[n]
// M=8192, N=128, K=1024. CTA tile 64x128 (grid 128), 256 thr, 4x8/thr.
// ---------------------------------------------------------------------------
__global__ __launch_bounds__(256) void out_proj_kernel(
    const float* __restrict__ Wc, const float* __restrict__ bc, float* __restrict__ out)
{
    extern __shared__ float sm[];
    float* As = sm;              // [64][128] swizzled
    float* Bs = sm + 64*128;     // [128][128] swizzled

    const int m0 = blockIdx.x * 64;
    const int tid = threadIdx.x;
    const int tx = tid & 15, ty = tid >> 4;

    ull acc[4][8];
    #pragma unroll
    for (int i = 0; i < 4; i++)
        #pragma unroll
        for (int j = 0; j < 8; j++) acc[i][j] = 0ULL;

    for (int kc = 0; kc < 1024; kc += 128) {
        __syncthreads();
        #pragma unroll
        for (int t = 0; t < 8; t++) {
            int idx = tid + 256*t;
            int r = idx >> 5, c4 = idx & 31;
            *(float4*)&As[r*128 + ((c4 ^ (r & 31)) << 2)] =
                *(const float4*)(g_O + (size_t)(m0+r)*1024 + kc + c4*4);
        }
        #pragma unroll
        for (int t = 0; t < 16; t++) {
            int idx = tid + 256*t;
            int r = idx >> 5, c4 = idx & 31;
            *(float4*)&Bs[r*128 + ((c4 ^ (r & 31)) << 2)] =
                *(const float4*)(Wc + (size_t)r*1024 + kc + c4*4);
        }
        __syncthreads();

        #pragma unroll 2
        for (int kk = 0; kk < 128; kk += 4) {
            int c4 = kk >> 2;
            ulonglong2 av[4], bv[8];
            #pragma unroll
            for (int i = 0; i < 4; i++) {
                int r = ty*4 + i;
                av[i] = *(const ulonglong2*)&As[r*128 + ((c4 ^ (r & 31)) << 2)];
            }
            #pragma unroll
            for (int j = 0; j < 8; j++) {
                int n = tx + 16*j;
                bv[j] = *(const ulonglong2*)&Bs[n*128 + ((c4 ^ (n & 31)) << 2)];
            }
            #pragma unroll
            for (int i = 0; i < 4; i++)
                #pragma unroll
                for (int j = 0; j < 8; j++) {
                    ffma2(acc[i][j], av[i].x, bv[j].x);
                    ffma2(acc[i][j], av[i].y, bv[j].y);
                }
        }
    }

    float bcv[8];
    #pragma unroll
    for (int j = 0; j < 8; j++) bcv[j] = bc[tx + 16*j];

    #pragma unroll
    for (int i = 0; i < 4; i++) {
        int m = m0 + ty*4 + i;
        float* op = out + (size_t)m*128;
        #pragma unroll
        for (int j = 0; j < 8; j++)
            op[tx + 16*j] = fsum2(acc[i][j]) + bcv[j];
    }
}

// ---------------------------------------------------------------------------
extern "C" void kernel_launch(void* const* d_in, const int* in_sizes, int n_in,
                              void* d_out, int out_size)
{
    const float* q    = (const float*)d_in[0];
    const float* k    = (const float*)d_in[1];
    const float* v    = (const float*)d_in[2];
    const float* mask = (const float*)d_in[3];
    const float* Wq   = (const float*)d_in[4];
    const float* Wk   = (const float*)d_in[5];
    const float* Wv   = (const float*)d_in[6];
    const float* Wc   = (const float*)d_in[7];
    const float* bc   = (const float*)d_in[8];
    float* out = (float*)d_out;

    const int qkv_smem  = 2*128*128*4;                                  // 128 KB
    const int attn_smem = (128*128 + 64*128 + 128*64 + 128*68)*4;       // ~162 KB
    const int outp_smem = (64*128 + 128*128)*4;                         // 96 KB

    cudaFuncSetAttribute(qkv_proj_kernel, cudaFuncAttributeMaxDynamicSharedMemorySize, qkv_smem);
    cudaFuncSetAttribute(attn_kernel, cudaFuncAttributeMaxDynamicSharedMemorySize, attn_smem);
    cudaFuncSetAttribute(out_proj_kernel, cudaFuncAttributeMaxDynamicSharedMemorySize, outp_smem);

    qkv_proj_kernel<<<dim3(8, 64, 3), 256, qkv_smem>>>(q, k, v, Wq, Wk, Wv);
    attn_kernel<<<dim3(8, 64), 256, attn_smem>>>(mask);
    out_proj_kernel<<<128, 256, outp_smem>>>(Wc, bc, out);
}

// round 3
// speedup vs baseline: 3.7979x; 3.7979x over previous
#include <cuda_runtime.h>
#include <cuda_bf16.h>

#define BB 8
#define SS 1024
#define EE 128
#define HH 8
#define DD 128

// Scratch planes (static device globals -- no runtime allocation allowed)
__device__ __nv_bfloat16 g_Qh[(size_t)BB*HH*SS*DD];
__device__ __nv_bfloat16 g_Ql[(size_t)BB*HH*SS*DD];
__device__ __nv_bfloat16 g_Kh[(size_t)BB*HH*SS*DD];
__device__ __nv_bfloat16 g_Kl[(size_t)BB*HH*SS*DD];
__device__ __nv_bfloat16 g_Vh[(size_t)BB*HH*SS*DD];
__device__ __nv_bfloat16 g_Vl[(size_t)BB*HH*SS*DD];
__device__ float g_O[(size_t)BB*SS*HH*DD];   // [B,S,H*D] fp32

// ---- warp-mma helpers ----
__device__ __forceinline__ void mma16816(float* c, const unsigned* a, const unsigned* b) {
    asm volatile(
        "mma.sync.aligned.m16n8k16.row.col.f32.bf16.bf16.f32 "
        "{%0,%1,%2,%3}, {%4,%5,%6,%7}, {%8,%9}, {%0,%1,%2,%3};\n"
        : "+f"(c[0]), "+f"(c[1]), "+f"(c[2]), "+f"(c[3])
        : "r"(a[0]), "r"(a[1]), "r"(a[2]), "r"(a[3]), "r"(b[0]), "r"(b[1]));
}
__device__ __forceinline__ void ldsm4(unsigned* r, unsigned addr) {
    asm volatile("ldmatrix.sync.aligned.m8n8.x4.shared.b16 {%0,%1,%2,%3}, [%4];"
        : "=r"(r[0]), "=r"(r[1]), "=r"(r[2]), "=r"(r[3]) : "r"(addr));
}
__device__ __forceinline__ void ldsm4t(unsigned* r, unsigned addr) {
    asm volatile("ldmatrix.sync.aligned.m8n8.x4.trans.shared.b16 {%0,%1,%2,%3}, [%4];"
        : "=r"(r[0]), "=r"(r[1]), "=r"(r[2]), "=r"(r[3]) : "r"(addr));
}
__device__ __forceinline__ unsigned cvt2(float hi, float lo) {
    unsigned r;
    asm("cvt.rn.bf16x2.f32 %0, %1, %2;" : "=r"(r) : "f"(hi), "f"(lo));
    return r;
}

// ---------------------------------------------------------------------------
// Fused QKV projection (fp32 FFMA, round-0 structure).
// Epilogue writes bf16 hi/lo planes into [B,H,S,D].
// ---------------------------------------------------------------------------
__global__ __launch_bounds__(256) void qkv_proj_kernel(
    const float* __restrict__ q, const float* __restrict__ k, const float* __restrict__ v,
    const float* __restrict__ Wq, const float* __restrict__ Wk, const float* __restrict__ Wv)
{
    __shared__ float As[16*128];   // As[kk][m]
    __shared__ float Bs[16*128];   // Bs[kk][n]

    const float* A; const float* W;
    __nv_bfloat16* Oh; __nv_bfloat16* Ol;
    if (blockIdx.z == 0)      { A = q; W = Wq; Oh = g_Qh; Ol = g_Ql; }
    else if (blockIdx.z == 1) { A = k; W = Wk; Oh = g_Kh; Ol = g_Kl; }
    else                      { A = v; W = Wv; Oh = g_Vh; Ol = g_Vl; }

    const int m0 = blockIdx.y * 128;
    const int h  = blockIdx.x;
    const int tid = threadIdx.x;
    const int ty = tid >> 4, tx = tid & 15;

    float acc[8][8];
    #pragma unroll
    for (int i = 0; i < 8; i++)
        #pragma unroll
        for (int j = 0; j < 8; j++) acc[i][j] = 0.f;

    for (int kc = 0; kc < 128; kc += 16) {
        #pragma unroll
        for (int q2 = 0; q2 < 2; q2++) {
            int fid = tid*2 + q2;
            int m  = fid >> 2;
            int kk = (fid & 3) << 2;
            float4 fa = *(const float4*)(A + (size_t)(m0+m)*128 + kc + kk);
            As[(kk+0)*128+m] = fa.x; As[(kk+1)*128+m] = fa.y;
            As[(kk+2)*128+m] = fa.z; As[(kk+3)*128+m] = fa.w;
            float4 fb = *(const float4*)(W + (size_t)(h*128+m)*128 + kc + kk);
            Bs[(kk+0)*128+m] = fb.x; Bs[(kk+1)*128+m] = fb.y;
            Bs[(kk+2)*128+m] = fb.z; Bs[(kk+3)*128+m] = fb.w;
        }
        __syncthreads();
        #pragma unroll
        for (int kk = 0; kk < 16; kk++) {
            float4 a0 = *(const float4*)&As[kk*128 + ty*8];
            float4 a1 = *(const float4*)&As[kk*128 + ty*8 + 4];
            float4 b0 = *(const float4*)&Bs[kk*128 + tx*8];
            float4 b1 = *(const float4*)&Bs[kk*128 + tx*8 + 4];
            float a_[8] = {a0.x,a0.y,a0.z,a0.w,a1.x,a1.y,a1.z,a1.w};
            float b_[8] = {b0.x,b0.y,b0.z,b0.w,b1.x,b1.y,b1.z,b1.w};
            #pragma unroll
            for (int i = 0; i < 8; i++)
                #pragma unroll
                for (int j = 0; j < 8; j++)
                    acc[i][j] += a_[i]*b_[j];
        }
        __syncthreads();
    }

    #pragma unroll
    for (int i = 0; i < 8; i++) {
        int m = m0 + ty*8 + i;
        int b_ = m >> 10, s_ = m & 1023;
        size_t off = (((size_t)(b_*HH + h))*SS + s_)*DD + tx*8;
        __align__(16) __nv_bfloat16 hv[8], lv[8];
        #pragma unroll
        for (int j = 0; j < 8; j++) {
            float x = acc[i][j];
            __nv_bfloat16 hb = __float2bfloat16(x);
            hv[j] = hb;
            lv[j] = __float2bfloat16(x - __bfloat162float(hb));
        }
        *(uint4*)(Oh + off) = *(uint4*)hv;
        *(uint4*)(Ol + off) = *(uint4*)lv;
    }
}

// ---------------------------------------------------------------------------
// Flash attention with mma.sync bf16 hi/lo split.
// CTA = 128 q-rows of one (b,h), 8 warps, each warp owns 16 q-rows.
// kv blocks of 64. Smem planes swizzled for ldmatrix (16B chunk ^ (row&7)).
// ---------------------------------------------------------------------------
__global__ __launch_bounds__(256, 1) void attn_kernel(const float* __restrict__ mask)
{
    extern __shared__ char sm[];
    uint4* sQh = (uint4*)sm;            // 128 rows x 16 chunks
    uint4* sQl = sQh + 128*16;
    uint4* sKh = sQl + 128*16;          // 64 rows
    uint4* sKl = sKh + 64*16;
    uint4* sVh = sKl + 64*16;
    uint4* sVl = sVh + 64*16;
    float* msk = (float*)(sVl + 64*16); // 64 floats

    const unsigned smem_u = (unsigned)__cvta_generic_to_shared(sm);
    const unsigned offQh = 0, offKh = 65536, offVh = 98304;

    const int tid  = threadIdx.x;
    const int lane = tid & 31;
    const int wid  = tid >> 5;
    const int wq0  = wid * 16;
    const int g    = lane >> 2;
    const int tig  = lane & 3;

    const int bh = blockIdx.y;
    const int b_ = bh >> 3, h = bh & 7;
    const int q0 = blockIdx.x * 128;

    const uint4* qh = (const uint4*)(g_Qh + ((size_t)bh*SS + q0)*DD);
    const uint4* ql = (const uint4*)(g_Ql + ((size_t)bh*SS + q0)*DD);
    const uint4* kh = (const uint4*)(g_Kh + (size_t)bh*SS*DD);
    const uint4* kl = (const uint4*)(g_Kl + (size_t)bh*SS*DD);
    const uint4* vh = (const uint4*)(g_Vh + (size_t)bh*SS*DD);
    const uint4* vl = (const uint4*)(g_Vl + (size_t)bh*SS*DD);
    const float* mb = mask + b_*SS;

    // load Q planes (swizzled)
    #pragma unroll
    for (int t = 0; t < 8; t++) {
        int idx = tid + 256*t;
        int r = idx >> 4, c = idx & 15;
        int phys = r*16 + (c ^ (r & 7));
        sQh[phys] = qh[idx];
        sQl[phys] = ql[idx];
    }

    float o[16][4];
    #pragma unroll
    for (int nt = 0; nt < 16; nt++)
        #pragma unroll
        for (int c = 0; c < 4; c++) o[nt][c] = 0.f;

    float m0s = -3.0e38f, m1s = -3.0e38f, l0s = 0.f, l1s = 0.f;
    const float scale = 0.08838834764831845f;  // 1/sqrt(128)

    // lane-derived ldmatrix geometry
    const int arow = wq0 + (lane & 7) + ((lane >> 3) & 1)*8;   // Q rows
    const int abit = lane >> 4;                                 // +chunk
    const int kb   = (lane & 7) + ((lane >> 4) & 1)*8;          // K row within n-pair
    const int kbit = (lane >> 3) & 1;
    const int vr   = (lane & 7) + ((lane >> 3) & 1)*8;          // V row within k-step
    const int vbit = (lane >> 4) & 1;

    for (int j0 = 0; j0 < SS; j0 += 64) {
        // load K/V planes + mask slice
        #pragma unroll
        for (int t = 0; t < 4; t++) {
            int idx = tid + 256*t;
            int r = idx >> 4, c = idx & 15;
            int phys = r*16 + (c ^ (r & 7));
            int gidx = (j0 >> 3)*16*16/16*8 + idx;  // = j0*16 + idx  (j0 rows * 16 chunks)
            gidx = j0*16 + idx;
            sKh[phys] = kh[gidx];
            sKl[phys] = kl[gidx];
            sVh[phys] = vh[gidx];
            sVl[phys] = vl[gidx];
        }
        if (tid < 64) msk[tid] = mb[j0 + tid];
        __syncthreads();

        // ---- S = Q K^T (16x64 per warp) ----
        float sacc[8][4];
        #pragma unroll
        for (int nt = 0; nt < 8; nt++)
            #pragma unroll
            for (int c = 0; c < 4; c++) sacc[nt][c] = 0.f;

        #pragma unroll
        for (int ks = 0; ks < 8; ks++) {
            unsigned a_h[4], a_l[4];
            int achk = 2*ks + abit;
            unsigned aaddr = smem_u + offQh + (unsigned)(arow*16 + (achk ^ (arow & 7)))*16;
            ldsm4(a_h, aaddr);
            ldsm4(a_l, aaddr + 32768);
            #pragma unroll
            for (int np = 0; np < 4; np++) {
                int brow = np*16 + kb;
                int bchk = 2*ks + kbit;
                unsigned baddr = smem_u + offKh + (unsigned)(brow*16 + (bchk ^ (brow & 7)))*16;
                unsigned b_h[4], b_l[4];
                ldsm4(b_h, baddr);
                ldsm4(b_l, baddr + 16384);
                mma16816(sacc[2*np],   a_h, b_h);
                mma16816(sacc[2*np],   a_h, b_l);
                mma16816(sacc[2*np],   a_l, b_h);
                mma16816(sacc[2*np+1], a_h, b_h + 2);
                mma16816(sacc[2*np+1], a_h, b_l + 2);
                mma16816(sacc[2*np+1], a_l, b_h + 2);
            }
        }

        // ---- online softmax on fragments ----
        float mx0 = -3.0e38f, mx1 = -3.0e38f;
        #pragma unroll
        for (int nt = 0; nt < 8; nt++) {
            float mk0 = msk[nt*8 + 2*tig];
            float mk1 = msk[nt*8 + 2*tig + 1];
            sacc[nt][0] = sacc[nt][0]*scale + mk0;
            sacc[nt][1] = sacc[nt][1]*scale + mk1;
            sacc[nt][2] = sacc[nt][2]*scale + mk0;
            sacc[nt][3] = sacc[nt][3]*scale + mk1;
            mx0 = fmaxf(mx0, fmaxf(sacc[nt][0], sacc[nt][1]));
            mx1 = fmaxf(mx1, fmaxf(sacc[nt][2], sacc[nt][3]));
        }
        #pragma unroll
        for (int mskb = 1; mskb <= 2; mskb <<= 1) {
            mx0 = fmaxf(mx0, __shfl_xor_sync(0xffffffffu, mx0, mskb));
            mx1 = fmaxf(mx1, __shfl_xor_sync(0xffffffffu, mx1, mskb));
        }
        float mn0 = fmaxf(m0s, mx0), mn1 = fmaxf(m1s, mx1);
        float al0 = __expf(m0s - mn0), al1 = __expf(m1s - mn1);
        m0s = mn0; m1s = mn1;

        float sum0 = 0.f, sum1 = 0.f;
        #pragma unroll
        for (int nt = 0; nt < 8; nt++) {
            float p0 = __expf(sacc[nt][0] - mn0);
            float p1 = __expf(sacc[nt][1] - mn0);
            float p2 = __expf(sacc[nt][2] - mn1);
            float p3 = __expf(sacc[nt][3] - mn1);
            sacc[nt][0] = p0; sacc[nt][1] = p1; sacc[nt][2] = p2; sacc[nt][3] = p3;
            sum0 += p0 + p1; sum1 += p2 + p3;
        }
        #pragma unroll
        for (int mskb = 1; mskb <= 2; mskb <<= 1) {
            sum0 += __shfl_xor_sync(0xffffffffu, sum0, mskb);
            sum1 += __shfl_xor_sync(0xffffffffu, sum1, mskb);
        }
        l0s = l0s*al0 + sum0;
        l1s = l1s*al1 + sum1;

        // rescale O
        #pragma unroll
        for (int nt = 0; nt < 16; nt++) {
            o[nt][0] *= al0; o[nt][1] *= al0;
            o[nt][2] *= al1; o[nt][3] *= al1;
        }

        // ---- O += P V ----
        #pragma unroll
        for (int kk = 0; kk < 4; kk++) {
            unsigned pah[4], pal[4];
            #pragma unroll
            for (int half = 0; half < 2; half++) {
                int nt = 2*kk + half;
                float p0 = sacc[nt][0], p1 = sacc[nt][1];
                float p2 = sacc[nt][2], p3 = sacc[nt][3];
                float h0 = __bfloat162float(__float2bfloat16(p0));
                float h1 = __bfloat162float(__float2bfloat16(p1));
                float h2 = __bfloat162float(__float2bfloat16(p2));
                float h3 = __bfloat162float(__float2bfloat16(p3));
                pah[2*half]   = cvt2(p1, p0);
                pah[2*half+1] = cvt2(p3, p2);
                pal[2*half]   = cvt2(p1 - h1, p0 - h0);
                pal[2*half+1] = cvt2(p3 - h3, p2 - h2);
            }
            // pah/pal order: [a0 (rows g, k 0-7), a1 (rows g+8, k 0-7), a2, a3]
            // built as: half0 -> a0,a1 ; half1 -> a2,a3  (matches layout)
            int vrow = kk*16 + vr;
            #pragma unroll
            for (int np = 0; np < 8; np++) {
                int vchk = 2*np + vbit;
                unsigned vaddr = smem_u + offVh + (unsigned)(vrow*16 + (vchk ^ (vrow & 7)))*16;
                unsigned vbh[4], vbl[4];
                ldsm4t(vbh, vaddr);
                ldsm4t(vbl, vaddr + 16384);
                mma16816(o[2*np],   pah, vbh);
                mma16816(o[2*np],   pah, vbl);
                mma16816(o[2*np],   pal, vbh);
                mma16816(o[2*np+1], pah, vbh + 2);
                mma16816(o[2*np+1], pah, vbl + 2);
                mma16816(o[2*np+1], pal, vbh + 2);
            }
        }
        __syncthreads();
    }

    // epilogue: normalize and write fp32 concat layout [B,S,H*D]
    float inv0 = 1.f / (l0s + 1e-12f);
    float inv1 = 1.f / (l1s + 1e-12f);
    int r0 = q0 + wq0 + g;
    float* orow0 = g_O + ((size_t)(b_*SS + r0))*(HH*DD) + h*DD;
    float* orow1 = orow0 + (size_t)8*(HH*DD);
    #pragma unroll
    for (int nt = 0; nt < 16; nt++) {
        int cc = nt*8 + 2*tig;
        *(float2*)(orow0 + cc) = make_float2(o[nt][0]*inv0, o[nt][1]*inv0);
        *(float2*)(orow1 + cc) = make_float2(o[nt][2]*inv1, o[nt][3]*inv1);
    }
}

// ---------------------------------------------------------------------------
// Output projection (round-0 fp32 FFMA): out[m][n] = sum_k O[m][k]*Wc[n][k] + bc[n]
// ---------------------------------------------------------------------------
__global__ __launch_bounds__(256) void out_proj_kernel(
    const float* __restrict__ Wc, const float* __restrict__ bc, float* __restrict__ out)
{
    __shared__ float As[16*128];
    __shared__ float Bs[16*128];

    const int m0 = blockIdx.x * 128;
    const int tid = threadIdx.x;
    const int ty = tid >> 4, tx = tid & 15;

    float acc[8][8];
    #pragma unroll
    for (int i = 0; i < 8; i++)
        #pragma unroll
        for (int j = 0; j < 8; j++) acc[i][j] = 0.f;

    for (int kc = 0; kc < 1024; kc += 16) {
        #pragma unroll
        for (int q2 = 0; q2 < 2; q2++) {
            int fid = tid*2 + q2;
            int m  = fid >> 2;
            int kk = (fid & 3) << 2;
            float4 fa = *(const float4*)(g_O + (size_t)(m0+m)*1024 + kc + kk);
            As[(kk+0)*128+m] = fa.x; As[(kk+1)*128+m] = fa.y;
            As[(kk+2)*128+m] = fa.z; As[(kk+3)*128+m] = fa.w;
            float4 fb = *(const float4*)(Wc + (size_t)m*1024 + kc + kk);
            Bs[(kk+0)*128+m] = fb.x; Bs[(kk+1)*128+m] = fb.y;
            Bs[(kk+2)*128+m] = fb.z; Bs[(kk+3)*128+m] = fb.w;
        }
        __syncthreads();
        #pragma unroll
        for (int kk = 0; kk < 16; kk++) {
            float4 a0 = *(const float4*)&As[kk*128 + ty*8];
            float4 a1 = *(const float4*)&As[kk*128 + ty*8 + 4];
            float4 b0 = *(const float4*)&Bs[kk*128 + tx*8];
            float4 b1 = *(const float4*)&Bs[kk*128 + tx*8 + 4];
            float a_[8] = {a0.x,a0.y,a0.z,a0.w,a1.x,a1.y,a1.z,a1.w};
            float b_[8] = {b0.x,b0.y,b0.z,b0.w,b1.x,b1.y,b1.z,b1.w};
            #pragma unroll
            for (int i = 0; i < 8; i++)
                #pragma unroll
                for (int j = 0; j < 8; j++)
                    acc[i][j] += a_[i]*b_[j];
        }
        __syncthreads();
    }

    float4 bb0 = *(const float4*)(bc + tx*8);
    float4 bb1 = *(const float4*)(bc + tx*8 + 4);
    #pragma unroll
    for (int i = 0; i < 8; i++) {
        int m = m0 + ty*8 + i;
        float* op = out + (size_t)m*128 + tx*8;
        *(float4*)op     = make_float4(acc[i][0]+bb0.x, acc[i][1]+bb0.y,
                                       acc[i][2]+bb0.z, acc[i][3]+bb0.w);
        *(float4*)(op+4) = make_float4(acc[i][4]+bb1.x, acc[i][5]+bb1.y,
                                       acc[i][6]+bb1.z, acc[i][7]+bb1.w);
    }
}

// ---------------------------------------------------------------------------
extern "C" void kernel_launch(void* const* d_in, const int* in_sizes, int n_in,
                              void* d_out, int out_size)
{
    const float* q    = (const float*)d_in[0];
    const float* k    = (const float*)d_in[1];
    const float* v    = (const float*)d_in[2];
    const float* mask = (const float*)d_in[3];
    const float* Wq   = (const float*)d_in[4];
    const float* Wk   = (const float*)d_in[5];
    const float* Wv   = (const float*)d_in[6];
    const float* Wc   = (const float*)d_in[7];
    const float* bc   = (const float*)d_in[8];
    float* out = (float*)d_out;

    const int attn_smem = 131072 + 256;   // Q(64K) + K(32K) + V(32K) + mask
    cudaFuncSetAttribute(attn_kernel, cudaFuncAttributeMaxDynamicSharedMemorySize, attn_smem);

    qkv_proj_kernel<<<dim3(8, 64, 3), 256>>>(q, k, v, Wq, Wk, Wv);
    attn_kernel<<<dim3(8, 64), 256, attn_smem>>>(mask);
    out_proj_kernel<<<64, 256>>>(Wc, bc, out);
}